// round 8
// baseline (speedup 1.0000x reference)
#include <cuda_runtime.h>
#include <cuda_bf16.h>
#include <cstdint>

// Problem constants
#define N_EMBED 512
#define DIMQ    64          // IN_MEM*OUT_MEM
#define NROWS   4096        // IN_G*OUT_G
#define KDIM    512
#define NDIM    512
#define QBLKS   (NROWS / 32)   // 128 quantize blocks

// Scratch (no cudaMalloc allowed)
__device__ __nv_bfloat16  d_WtHi[NDIM * KDIM];    // W^T hi  [n][k]
__device__ __nv_bfloat16  d_WtLo[NDIM * KDIM];    // W^T lo  [n][k]
__device__ double         d_diff_blk[QBLKS];      // per-block diff partials

// ---------------------------------------------------------------------------
// helpers
// ---------------------------------------------------------------------------
__device__ __forceinline__ uint32_t smem_u32(const void* p) {
    uint32_t a;
    asm("{ .reg .u64 t; cvta.to.shared.u64 t, %1; cvt.u32.u64 %0, t; }" : "=r"(a) : "l"(p));
    return a;
}
__device__ __forceinline__ void split2(float a, float b, uint32_t& h, uint32_t& l) {
    __nv_bfloat16 ah = __float2bfloat16_rn(a);
    __nv_bfloat16 bh = __float2bfloat16_rn(b);
    __nv_bfloat16 al = __float2bfloat16_rn(a - __bfloat162float(ah));
    __nv_bfloat16 bl = __float2bfloat16_rn(b - __bfloat162float(bh));
    __nv_bfloat162 hv; hv.x = ah; hv.y = bh;
    __nv_bfloat162 lv; lv.x = al; lv.y = bl;
    h = *(uint32_t*)&hv; l = *(uint32_t*)&lv;
}
__device__ __forceinline__ void ldsm4(uint32_t* r, uint32_t addr) {
    asm volatile("ldmatrix.sync.aligned.m8n8.x4.shared.b16 {%0,%1,%2,%3}, [%4];"
                 : "=r"(r[0]), "=r"(r[1]), "=r"(r[2]), "=r"(r[3]) : "r"(addr));
}
__device__ __forceinline__ void mma16816(float* c, const uint32_t* a,
                                         uint32_t b0, uint32_t b1) {
    asm volatile("mma.sync.aligned.m16n8k16.row.col.f32.bf16.bf16.f32 "
                 "{%0,%1,%2,%3}, {%4,%5,%6,%7}, {%8,%9}, {%0,%1,%2,%3};"
                 : "+f"(c[0]), "+f"(c[1]), "+f"(c[2]), "+f"(c[3])
                 : "r"(a[0]), "r"(a[1]), "r"(a[2]), "r"(a[3]), "r"(b0), "r"(b1));
}

// ---------------------------------------------------------------------------
// quantize v3: register-blocked dots (32 rows/block, thread = 4 rows x 16
// codes strided by 128 for coalescing), ||e||^2 accumulated inline (no init
// kernel, no global e2 table), argmin with first-index tie-break, then split
// hi/lo straight into d_WtHi/d_WtLo. Per-block diff partial -> d_diff_blk.
// grid 128 x 256 threads.
// ---------------------------------------------------------------------------
__global__ __launch_bounds__(256) void quantize_kernel(
    const float* __restrict__ w,        // [4096,64] flat
    const float* __restrict__ embed)    // [64,512]
{
    __shared__ float  ws[32][DIMQ];     // w tile
    __shared__ double blk_diff[8];

    const int tid = threadIdx.x;
    const int ty  = tid >> 5;           // warp id = row group (4 rows)
    const int tx  = tid & 31;           // lane
    const int row0 = blockIdx.x * 32;

    // load w tile: thread -> row tid>>3, cols (tid&7)*8 .. +8
    {
        const int r = tid >> 3;
        const int c = (tid & 7) * 8;
        const float4* src = (const float4*)(w + (size_t)(row0 + r) * DIMQ + c);
        *(float4*)&ws[r][c]     = __ldg(src);
        *(float4*)&ws[r][c + 4] = __ldg(src + 1);
    }
    __syncthreads();

    // dots: acc[r][g*4+j] for code c = g*128 + tx*4 + j ; e2acc = ||e_c||^2
    float acc[4][16];
    float e2acc[16];
    #pragma unroll
    for (int c = 0; c < 16; ++c) e2acc[c] = 0.f;
    #pragma unroll
    for (int r = 0; r < 4; ++r)
        #pragma unroll
        for (int c = 0; c < 16; ++c) acc[r][c] = 0.f;

    #pragma unroll 2
    for (int d = 0; d < DIMQ; ++d) {
        float e[16];
        #pragma unroll
        for (int g = 0; g < 4; ++g)
            *(float4*)&e[g * 4] = __ldg((const float4*)(embed + d * N_EMBED + g * 128 + tx * 4));
        float wv[4];
        #pragma unroll
        for (int r = 0; r < 4; ++r) wv[r] = ws[ty * 4 + r][d];
        #pragma unroll
        for (int c = 0; c < 16; ++c) e2acc[c] += e[c] * e[c];
        #pragma unroll
        for (int r = 0; r < 4; ++r)
            #pragma unroll
            for (int c = 0; c < 16; ++c)
                acc[r][c] += wv[r] * e[c];
    }

    // per-row argmin + quant scatter
    float diff_local = 0.f;
    #pragma unroll
    for (int r = 0; r < 4; ++r) {
        float best = 3.4e38f;
        int   bidx = 0;
        #pragma unroll
        for (int g = 0; g < 4; ++g)
            #pragma unroll
            for (int j = 0; j < 4; ++j) {
                int c = g * 128 + tx * 4 + j;       // ascending within thread
                float s = e2acc[g * 4 + j] - 2.f * acc[r][g * 4 + j];
                if (s < best) { best = s; bidx = c; }
            }
        #pragma unroll
        for (int off = 16; off >= 1; off >>= 1) {
            float ob = __shfl_xor_sync(0xffffffffu, best, off);
            int   oi = __shfl_xor_sync(0xffffffffu, bidx, off);
            if (ob < best || (ob == best && oi < bidx)) { best = ob; bidx = oi; }
        }
        // all lanes agree on bidx for this row
        const int rl  = ty * 4 + r;
        const int row = row0 + rl;
        const int ig = row >> 6;
        const int og = row & 63;
        // lane covers om = tx&7, i pair = (tx>>3)*2
        const int om = tx & 7;
        const int i0 = (tx >> 3) * 2;
        const int d0 = i0 * 8 + om;
        const int d1 = d0 + 8;
        float q0 = __ldg(embed + d0 * N_EMBED + bidx);
        float q1 = __ldg(embed + d1 * N_EMBED + bidx);
        float w0 = ws[rl][d0], w1 = ws[rl][d1];
        float df0 = q0 - w0, df1 = q1 - w1;
        diff_local += df0 * df0 + df1 * df1;
        uint32_t h, l;
        split2(q0, q1, h, l);
        const size_t off_nk = (size_t)(og * 8 + om) * KDIM + ig * 8 + i0;
        *(uint32_t*)&d_WtHi[off_nk] = h;
        *(uint32_t*)&d_WtLo[off_nk] = l;
    }

    // block-reduce diff -> per-block partial (no atomics)
    #pragma unroll
    for (int off = 16; off >= 1; off >>= 1)
        diff_local += __shfl_xor_sync(0xffffffffu, diff_local, off);
    if (tx == 0) blk_diff[ty] = (double)diff_local;
    __syncthreads();
    if (tid == 0) {
        double s = 0.0;
        #pragma unroll
        for (int i = 0; i < 8; ++i) s += blk_diff[i];
        d_diff_blk[blockIdx.x] = s;
    }
}

// ---------------------------------------------------------------------------
// HMMA GEMM: C[8192,512] = x @ W via bf16 split (3 products), fp32 accum.
// CTA 128x128, 8 warps (warp tile 32x64), BK=32 fp32 per chunk, 16 chunks,
// double-buffered smem, cp.async for W, mma.sync bf16. 2 CTAs/SM (1 wave).
// CTA (0,0) thread 0 also reduces d_diff_blk and writes the diff scalar.
// ---------------------------------------------------------------------------
#define BK      32
#define NCH     (KDIM / BK)         // 16
#define RS      80                  // smem row stride bytes
#define MATB    (128 * RS)          // 10240 per matrix
#define STAGEB  (4 * MATB)          // 40960 per stage (Ahi, Alo, Whi, Wlo)
#define SMEMB   (2 * STAGEB)        // 81920

__global__ __launch_bounds__(256, 2) void gemm_mma_kernel(
    const float* __restrict__ A,    // x [B,512]
    float* __restrict__ C,          // res [B,512] (+ diff scalar)
    long n_res, long out_total)
{
    extern __shared__ char smem[];
    const uint32_t sb = smem_u32(smem);
    const int tid  = threadIdx.x;
    const int lane = tid & 31;
    const int wid  = tid >> 5;
    const int m0 = blockIdx.y * 128;
    const int n0 = blockIdx.x * 128;
    const int wm = (wid & 3) * 32;      // warp M origin in tile
    const int wn = (wid >> 2) * 64;     // warp N origin in tile

    // diff scalar: quantize kernel completed before this launch
    if (blockIdx.x == 0 && blockIdx.y == 0 && tid == 0 && out_total > n_res) {
        double s = 0.0;
        #pragma unroll 8
        for (int i = 0; i < QBLKS; ++i) s += d_diff_blk[i];
        C[n_res] = (float)(s * (1.0 / (double)(NROWS * DIMQ)));
    }

    const uint32_t aOff = (uint32_t)(wm + (lane & 15)) * RS + ((lane >> 4) * 16);
    const uint32_t bOff = (uint32_t)(wn + ((lane >> 4) * 8) + (lane & 7)) * RS
                        + (((lane >> 3) & 1) * 16);

    const int ar = tid >> 1;
    const int ac = (tid & 1) * 16;
    const float* aG = A + (size_t)(m0 + ar) * KDIM + ac;
    const uint32_t aStoreOff = (uint32_t)ar * RS + (uint32_t)ac * 2;

    const int wrow = tid & 127;
    const __nv_bfloat16* wG = ((tid < 128) ? d_WtHi : d_WtLo) + (size_t)(n0 + wrow) * KDIM;
    const uint32_t wStoreOff = ((tid < 128) ? 0u : (uint32_t)MATB) + (uint32_t)wrow * RS;

    float acc[2][8][4];
    #pragma unroll
    for (int mt = 0; mt < 2; ++mt)
        #pragma unroll
        for (int nt = 0; nt < 8; ++nt)
            #pragma unroll
            for (int q = 0; q < 4; ++q) acc[mt][nt][q] = 0.f;

    float aReg[16];

    #define CPW(kc, stage) do {                                                   \
        uint32_t _dst = sb + (stage) * STAGEB + 2 * MATB + wStoreOff;             \
        const char* _src = (const char*)(wG + (kc) * BK);                         \
        _Pragma("unroll")                                                         \
        for (int _j = 0; _j < 4; ++_j)                                            \
            asm volatile("cp.async.cg.shared.global [%0], [%1], 16;"              \
                         :: "r"(_dst + _j * 16), "l"(_src + _j * 16) : "memory"); \
        asm volatile("cp.async.commit_group;" ::: "memory");                      \
    } while (0)

    #define LDA(kc) do {                                                          \
        const float4* _p = (const float4*)(aG + (kc) * BK);                       \
        _Pragma("unroll")                                                         \
        for (int _j = 0; _j < 4; ++_j) *(float4*)&aReg[_j * 4] = __ldg(_p + _j);  \
    } while (0)

    #define STA(stage) do {                                                       \
        uint32_t _base = sb + (stage) * STAGEB + aStoreOff;                       \
        _Pragma("unroll")                                                         \
        for (int _h = 0; _h < 2; ++_h) {                                          \
            uint32_t _hi[4], _lo[4];                                              \
            _Pragma("unroll")                                                     \
            for (int _q = 0; _q < 4; ++_q)                                        \
                split2(aReg[_h * 8 + _q * 2], aReg[_h * 8 + _q * 2 + 1],          \
                       _hi[_q], _lo[_q]);                                         \
            asm volatile("st.shared.v4.b32 [%0], {%1,%2,%3,%4};"                  \
                :: "r"(_base + _h * 16),                                          \
                   "r"(_hi[0]), "r"(_hi[1]), "r"(_hi[2]), "r"(_hi[3]) : "memory");\
            asm volatile("st.shared.v4.b32 [%0], {%1,%2,%3,%4};"                  \
                :: "r"(_base + MATB + _h * 16),                                   \
                   "r"(_lo[0]), "r"(_lo[1]), "r"(_lo[2]), "r"(_lo[3]) : "memory");\
        }                                                                         \
    } while (0)

    #define COMPUTE(stage) do {                                                   \
        uint32_t _Ab = sb + (stage) * STAGEB;                                     \
        uint32_t _Bb = _Ab + 2 * MATB;                                            \
        _Pragma("unroll")                                                         \
        for (int _ks = 0; _ks < 2; ++_ks) {                                       \
            uint32_t _ahi[2][4], _alo[2][4], _bf[4][4];                           \
            _Pragma("unroll")                                                     \
            for (int _mt = 0; _mt < 2; ++_mt) {                                   \
                uint32_t _ad = _Ab + aOff + _mt * 16 * RS + _ks * 32;             \
                ldsm4(_ahi[_mt], _ad);                                            \
                ldsm4(_alo[_mt], _ad + MATB);                                     \
            }                                                                     \
            _Pragma("unroll")                                                     \
            for (int _p = 0; _p < 4; ++_p)                                        \
                ldsm4(_bf[_p], _Bb + bOff + _p * 16 * RS + _ks * 32);             \
            _Pragma("unroll")                                                     \
            for (int _mt = 0; _mt < 2; ++_mt)                                     \
                _Pragma("unroll")                                                 \
                for (int _nt = 0; _nt < 8; ++_nt) {                               \
                    uint32_t _b0 = _bf[_nt >> 1][(_nt & 1) * 2];                  \
                    uint32_t _b1 = _bf[_nt >> 1][(_nt & 1) * 2 + 1];              \
                    mma16816(acc[_mt][_nt], _ahi[_mt], _b0, _b1);                 \
                    mma16816(acc[_mt][_nt], _alo[_mt], _b0, _b1);                 \
                }                                                                 \
            _Pragma("unroll")                                                     \
            for (int _p = 0; _p < 4; ++_p)                                        \
                ldsm4(_bf[_p], _Bb + MATB + bOff + _p * 16 * RS + _ks * 32);      \
            _Pragma("unroll")                                                     \
            for (int _mt = 0; _mt < 2; ++_mt)                                     \
                _Pragma("unroll")                                                 \
                for (int _nt = 0; _nt < 8; ++_nt)                                 \
                    mma16816(acc[_mt][_nt], _ahi[_mt],                            \
                             _bf[_nt >> 1][(_nt & 1) * 2],                        \
                             _bf[_nt >> 1][(_nt & 1) * 2 + 1]);                   \
        }                                                                         \
    } while (0)

    CPW(0, 0);
    LDA(0);
    STA(0);
    asm volatile("cp.async.wait_group 0;" ::: "memory");
    __syncthreads();

    for (int kc = 0; kc < NCH; ++kc) {
        const int st = kc & 1;
        if (kc + 1 < NCH) {
            CPW(kc + 1, st ^ 1);
            LDA(kc + 1);
        }
        COMPUTE(st);
        if (kc + 1 < NCH) {
            STA(st ^ 1);
            asm volatile("cp.async.wait_group 0;" ::: "memory");
            __syncthreads();
        }
    }

    #pragma unroll
    for (int mt = 0; mt < 2; ++mt) {
        int row = m0 + wm + mt * 16 + (lane >> 2);
        #pragma unroll
        for (int nt = 0; nt < 8; ++nt) {
            int col = n0 + wn + nt * 8 + (lane & 3) * 2;
            *(float2*)&C[(size_t)row * NDIM + col] =
                make_float2(acc[mt][nt][0], acc[mt][nt][1]);
            *(float2*)&C[(size_t)(row + 8) * NDIM + col] =
                make_float2(acc[mt][nt][2], acc[mt][nt][3]);
        }
    }
}

// ---------------------------------------------------------------------------
// launch: 2 kernels total
// ---------------------------------------------------------------------------
extern "C" void kernel_launch(void* const* d_in, const int* in_sizes, int n_in,
                              void* d_out, int out_size) {
    const float* x      = (const float*)d_in[0];
    const float* weight = (const float*)d_in[1];
    const float* embed  = (const float*)d_in[2];
    float* out = (float*)d_out;

    const int b = in_sizes[0] / KDIM;              // 8192

    quantize_kernel<<<QBLKS, 256>>>(weight, embed);

    static int smem_set = 0;
    if (!smem_set) {
        cudaFuncSetAttribute(gemm_mma_kernel,
                             cudaFuncAttributeMaxDynamicSharedMemorySize, SMEMB);
        smem_set = 1;
    }
    dim3 grid(NDIM / 128, b / 128);                // (4, 64)
    gemm_mma_kernel<<<grid, 256, SMEMB>>>(x, out, (long)b * NDIM, (long)out_size);
}

// round 9
// speedup vs baseline: 1.3157x; 1.3157x over previous
#include <cuda_runtime.h>
#include <cuda_bf16.h>
#include <cstdint>

// Problem constants
#define N_EMBED 512
#define DIMQ    64          // IN_MEM*OUT_MEM
#define NROWS   4096        // IN_G*OUT_G
#define KDIM    512
#define NDIM    512
#define BDIM    8192
#define QBLKS   (NROWS / 32)   // 128 quantize blocks

// Scratch (no cudaMalloc allowed)
__device__ __nv_bfloat16  d_WtHi[NDIM * KDIM];    // W^T hi  [n][k]
__device__ __nv_bfloat16  d_WtLo[NDIM * KDIM];    // W^T lo  [n][k]
__device__ __nv_bfloat16  d_XHi[BDIM * KDIM];     // x hi    [m][k]
__device__ __nv_bfloat16  d_XLo[BDIM * KDIM];     // x lo    [m][k]
__device__ double         d_diff_blk[QBLKS];      // per-block diff partials

// ---------------------------------------------------------------------------
// helpers
// ---------------------------------------------------------------------------
__device__ __forceinline__ uint32_t smem_u32(const void* p) {
    uint32_t a;
    asm("{ .reg .u64 t; cvta.to.shared.u64 t, %1; cvt.u32.u64 %0, t; }" : "=r"(a) : "l"(p));
    return a;
}
__device__ __forceinline__ void split2(float a, float b, uint32_t& h, uint32_t& l) {
    __nv_bfloat16 ah = __float2bfloat16_rn(a);
    __nv_bfloat16 bh = __float2bfloat16_rn(b);
    __nv_bfloat16 al = __float2bfloat16_rn(a - __bfloat162float(ah));
    __nv_bfloat16 bl = __float2bfloat16_rn(b - __bfloat162float(bh));
    __nv_bfloat162 hv; hv.x = ah; hv.y = bh;
    __nv_bfloat162 lv; lv.x = al; lv.y = bl;
    h = *(uint32_t*)&hv; l = *(uint32_t*)&lv;
}
__device__ __forceinline__ void ldsm4(uint32_t* r, uint32_t addr) {
    asm volatile("ldmatrix.sync.aligned.m8n8.x4.shared.b16 {%0,%1,%2,%3}, [%4];"
                 : "=r"(r[0]), "=r"(r[1]), "=r"(r[2]), "=r"(r[3]) : "r"(addr));
}
__device__ __forceinline__ void mma16816(float* c, const uint32_t* a,
                                         uint32_t b0, uint32_t b1) {
    asm volatile("mma.sync.aligned.m16n8k16.row.col.f32.bf16.bf16.f32 "
                 "{%0,%1,%2,%3}, {%4,%5,%6,%7}, {%8,%9}, {%0,%1,%2,%3};"
                 : "+f"(c[0]), "+f"(c[1]), "+f"(c[2]), "+f"(c[3])
                 : "r"(a[0]), "r"(a[1]), "r"(a[2]), "r"(a[3]), "r"(b0), "r"(b1));
}

// ---------------------------------------------------------------------------
// quantize v3 (unchanged from R8): 32 rows/block, thread = 4 rows x 16 codes,
// ||e||^2 accumulated inline, argmin with first-index tie-break, split hi/lo
// straight into d_WtHi/d_WtLo. Per-block diff partial -> d_diff_blk.
// ---------------------------------------------------------------------------
__global__ __launch_bounds__(256) void quantize_kernel(
    const float* __restrict__ w,        // [4096,64] flat
    const float* __restrict__ embed)    // [64,512]
{
    __shared__ float  ws[32][DIMQ];
    __shared__ double blk_diff[8];

    const int tid = threadIdx.x;
    const int ty  = tid >> 5;
    const int tx  = tid & 31;
    const int row0 = blockIdx.x * 32;

    {
        const int r = tid >> 3;
        const int c = (tid & 7) * 8;
        const float4* src = (const float4*)(w + (size_t)(row0 + r) * DIMQ + c);
        *(float4*)&ws[r][c]     = __ldg(src);
        *(float4*)&ws[r][c + 4] = __ldg(src + 1);
    }
    __syncthreads();

    float acc[4][16];
    float e2acc[16];
    #pragma unroll
    for (int c = 0; c < 16; ++c) e2acc[c] = 0.f;
    #pragma unroll
    for (int r = 0; r < 4; ++r)
        #pragma unroll
        for (int c = 0; c < 16; ++c) acc[r][c] = 0.f;

    #pragma unroll 2
    for (int d = 0; d < DIMQ; ++d) {
        float e[16];
        #pragma unroll
        for (int g = 0; g < 4; ++g)
            *(float4*)&e[g * 4] = __ldg((const float4*)(embed + d * N_EMBED + g * 128 + tx * 4));
        float wv[4];
        #pragma unroll
        for (int r = 0; r < 4; ++r) wv[r] = ws[ty * 4 + r][d];
        #pragma unroll
        for (int c = 0; c < 16; ++c) e2acc[c] += e[c] * e[c];
        #pragma unroll
        for (int r = 0; r < 4; ++r)
            #pragma unroll
            for (int c = 0; c < 16; ++c)
                acc[r][c] += wv[r] * e[c];
    }

    float diff_local = 0.f;
    #pragma unroll
    for (int r = 0; r < 4; ++r) {
        float best = 3.4e38f;
        int   bidx = 0;
        #pragma unroll
        for (int g = 0; g < 4; ++g)
            #pragma unroll
            for (int j = 0; j < 4; ++j) {
                int c = g * 128 + tx * 4 + j;
                float s = e2acc[g * 4 + j] - 2.f * acc[r][g * 4 + j];
                if (s < best) { best = s; bidx = c; }
            }
        #pragma unroll
        for (int off = 16; off >= 1; off >>= 1) {
            float ob = __shfl_xor_sync(0xffffffffu, best, off);
            int   oi = __shfl_xor_sync(0xffffffffu, bidx, off);
            if (ob < best || (ob == best && oi < bidx)) { best = ob; bidx = oi; }
        }
        const int rl  = ty * 4 + r;
        const int row = row0 + rl;
        const int ig = row >> 6;
        const int og = row & 63;
        const int om = tx & 7;
        const int i0 = (tx >> 3) * 2;
        const int d0 = i0 * 8 + om;
        const int d1 = d0 + 8;
        float q0 = __ldg(embed + d0 * N_EMBED + bidx);
        float q1 = __ldg(embed + d1 * N_EMBED + bidx);
        float w0 = ws[rl][d0], w1 = ws[rl][d1];
        float df0 = q0 - w0, df1 = q1 - w1;
        diff_local += df0 * df0 + df1 * df1;
        uint32_t h, l;
        split2(q0, q1, h, l);
        const size_t off_nk = (size_t)(og * 8 + om) * KDIM + ig * 8 + i0;
        *(uint32_t*)&d_WtHi[off_nk] = h;
        *(uint32_t*)&d_WtLo[off_nk] = l;
    }

    #pragma unroll
    for (int off = 16; off >= 1; off >>= 1)
        diff_local += __shfl_xor_sync(0xffffffffu, diff_local, off);
    if (tx == 0) blk_diff[ty] = (double)diff_local;
    __syncthreads();
    if (tid == 0) {
        double s = 0.0;
        #pragma unroll
        for (int i = 0; i < 8; ++i) s += blk_diff[i];
        d_diff_blk[blockIdx.x] = s;
    }
}

// ---------------------------------------------------------------------------
// xsplit: x fp32 -> (hi, lo) bf16 arrays. Extra block 2048 reduces the diff
// partials (runs after quantize; hidden under the copy blocks).
// grid 2049 x 256 threads; 8 floats per thread.
// ---------------------------------------------------------------------------
__global__ __launch_bounds__(256) void xsplit_kernel(
    const float* __restrict__ x,
    float* __restrict__ out, long n_res, long out_total)
{
    if (blockIdx.x == 2048) {
        if (threadIdx.x == 0 && out_total > n_res) {
            double s = 0.0;
            #pragma unroll 8
            for (int i = 0; i < QBLKS; ++i) s += d_diff_blk[i];
            out[n_res] = (float)(s * (1.0 / (double)(NROWS * DIMQ)));
        }
        return;
    }
    const size_t base = ((size_t)blockIdx.x * 256 + threadIdx.x) * 8;
    float4 v0 = __ldg((const float4*)(x + base));
    float4 v1 = __ldg((const float4*)(x + base + 4));
    uint32_t h[4], l[4];
    split2(v0.x, v0.y, h[0], l[0]);
    split2(v0.z, v0.w, h[1], l[1]);
    split2(v1.x, v1.y, h[2], l[2]);
    split2(v1.z, v1.w, h[3], l[3]);
    *(uint4*)&d_XHi[base] = make_uint4(h[0], h[1], h[2], h[3]);
    *(uint4*)&d_XLo[base] = make_uint4(l[0], l[1], l[2], l[3]);
}

// ---------------------------------------------------------------------------
// HMMA GEMM v2: C = x @ W via bf16 split (3 products), fp32 accum.
// CTA 128x128, 8 warps (warp tile 32x64), BK=32, 16 chunks, double-buffered
// smem; ALL operands via cp.async (A pre-split by xsplit). 2 CTAs/SM.
// ---------------------------------------------------------------------------
#define BK      32
#define NCH     (KDIM / BK)         // 16
#define RS      80                  // smem row stride bytes (64B data + pad)
#define MATB    (128 * RS)          // 10240 per matrix
#define STAGEB  (4 * MATB)          // 40960 per stage (Ahi, Alo, Whi, Wlo)
#define SMEMB   (2 * STAGEB)        // 81920

__global__ __launch_bounds__(256, 2) void gemm_mma_kernel(
    float* __restrict__ C)          // res [B,512]
{
    extern __shared__ char smem[];
    const uint32_t sb = smem_u32(smem);
    const int tid  = threadIdx.x;
    const int lane = tid & 31;
    const int wid  = tid >> 5;
    const int m0 = blockIdx.y * 128;
    const int n0 = blockIdx.x * 128;
    const int wm = (wid & 3) * 32;
    const int wn = (wid >> 2) * 64;

    const uint32_t aOff = (uint32_t)(wm + (lane & 15)) * RS + ((lane >> 4) * 16);
    const uint32_t bOff = (uint32_t)(wn + ((lane >> 4) * 8) + (lane & 7)) * RS
                        + (((lane >> 3) & 1) * 16);

    // cp.async sources: half the threads handle hi planes, half lo planes
    const int prow = tid & 127;
    const __nv_bfloat16* aG = ((tid < 128) ? d_XHi : d_XLo) + (size_t)(m0 + prow) * KDIM;
    const __nv_bfloat16* wG = ((tid < 128) ? d_WtHi : d_WtLo) + (size_t)(n0 + prow) * KDIM;
    const uint32_t aSt = ((tid < 128) ? 0u : (uint32_t)MATB) + (uint32_t)prow * RS;
    const uint32_t wSt = aSt + 2 * MATB;

    float acc[2][8][4];
    #pragma unroll
    for (int mt = 0; mt < 2; ++mt)
        #pragma unroll
        for (int nt = 0; nt < 8; ++nt)
            #pragma unroll
            for (int q = 0; q < 4; ++q) acc[mt][nt][q] = 0.f;

    #define CPALL(kc, stage) do {                                                 \
        uint32_t _ad = sb + (stage) * STAGEB + aSt;                               \
        uint32_t _wd = sb + (stage) * STAGEB + wSt;                               \
        const char* _as = (const char*)(aG + (kc) * BK);                          \
        const char* _ws = (const char*)(wG + (kc) * BK);                          \
        _Pragma("unroll")                                                         \
        for (int _j = 0; _j < 4; ++_j)                                            \
            asm volatile("cp.async.cg.shared.global [%0], [%1], 16;"              \
                         :: "r"(_ad + _j * 16), "l"(_as + _j * 16) : "memory");   \
        _Pragma("unroll")                                                         \
        for (int _j = 0; _j < 4; ++_j)                                            \
            asm volatile("cp.async.cg.shared.global [%0], [%1], 16;"              \
                         :: "r"(_wd + _j * 16), "l"(_ws + _j * 16) : "memory");   \
        asm volatile("cp.async.commit_group;" ::: "memory");                      \
    } while (0)

    #define COMPUTE(stage) do {                                                   \
        uint32_t _Ab = sb + (stage) * STAGEB;                                     \
        uint32_t _Bb = _Ab + 2 * MATB;                                            \
        _Pragma("unroll")                                                         \
        for (int _ks = 0; _ks < 2; ++_ks) {                                       \
            uint32_t _ahi[2][4], _alo[2][4], _bf[4][4];                           \
            _Pragma("unroll")                                                     \
            for (int _mt = 0; _mt < 2; ++_mt) {                                   \
                uint32_t _ad = _Ab + aOff + _mt * 16 * RS + _ks * 32;             \
                ldsm4(_ahi[_mt], _ad);                                            \
                ldsm4(_alo[_mt], _ad + MATB);                                     \
            }                                                                     \
            _Pragma("unroll")                                                     \
            for (int _p = 0; _p < 4; ++_p)                                        \
                ldsm4(_bf[_p], _Bb + bOff + _p * 16 * RS + _ks * 32);             \
            _Pragma("unroll")                                                     \
            for (int _mt = 0; _mt < 2; ++_mt)                                     \
                _Pragma("unroll")                                                 \
                for (int _nt = 0; _nt < 8; ++_nt) {                               \
                    uint32_t _b0 = _bf[_nt >> 1][(_nt & 1) * 2];                  \
                    uint32_t _b1 = _bf[_nt >> 1][(_nt & 1) * 2 + 1];              \
                    mma16816(acc[_mt][_nt], _ahi[_mt], _b0, _b1);                 \
                    mma16816(acc[_mt][_nt], _alo[_mt], _b0, _b1);                 \
                }                                                                 \
            _Pragma("unroll")                                                     \
            for (int _p = 0; _p < 4; ++_p)                                        \
                ldsm4(_bf[_p], _Bb + MATB + bOff + _p * 16 * RS + _ks * 32);      \
            _Pragma("unroll")                                                     \
            for (int _mt = 0; _mt < 2; ++_mt)                                     \
                _Pragma("unroll")                                                 \
                for (int _nt = 0; _nt < 8; ++_nt)                                 \
                    mma16816(acc[_mt][_nt], _ahi[_mt],                            \
                             _bf[_nt >> 1][(_nt & 1) * 2],                        \
                             _bf[_nt >> 1][(_nt & 1) * 2 + 1]);                   \
        }                                                                         \
    } while (0)

    CPALL(0, 0);
    asm volatile("cp.async.wait_group 0;" ::: "memory");
    __syncthreads();

    for (int kc = 0; kc < NCH; ++kc) {
        const int st = kc & 1;
        if (kc + 1 < NCH) CPALL(kc + 1, st ^ 1);
        COMPUTE(st);
        if (kc + 1 < NCH) {
            asm volatile("cp.async.wait_group 0;" ::: "memory");
            __syncthreads();
        }
    }

    #pragma unroll
    for (int mt = 0; mt < 2; ++mt) {
        int row = m0 + wm + mt * 16 + (lane >> 2);
        #pragma unroll
        for (int nt = 0; nt < 8; ++nt) {
            int col = n0 + wn + nt * 8 + (lane & 3) * 2;
            *(float2*)&C[(size_t)row * NDIM + col] =
                make_float2(acc[mt][nt][0], acc[mt][nt][1]);
            *(float2*)&C[(size_t)(row + 8) * NDIM + col] =
                make_float2(acc[mt][nt][2], acc[mt][nt][3]);
        }
    }
}

// ---------------------------------------------------------------------------
// launch: 3 kernels
// ---------------------------------------------------------------------------
extern "C" void kernel_launch(void* const* d_in, const int* in_sizes, int n_in,
                              void* d_out, int out_size) {
    const float* x      = (const float*)d_in[0];
    const float* weight = (const float*)d_in[1];
    const float* embed  = (const float*)d_in[2];
    float* out = (float*)d_out;

    const int b = in_sizes[0] / KDIM;              // 8192

    quantize_kernel<<<QBLKS, 256>>>(weight, embed);
    xsplit_kernel<<<2049, 256>>>(x, out, (long)b * NDIM, (long)out_size);

    static int smem_set = 0;
    if (!smem_set) {
        cudaFuncSetAttribute(gemm_mma_kernel,
                             cudaFuncAttributeMaxDynamicSharedMemorySize, SMEMB);
        smem_set = 1;
    }
    dim3 grid(NDIM / 128, b / 128);                // (4, 64)
    gemm_mma_kernel<<<grid, 256, SMEMB>>>(out);
}

// round 10
// speedup vs baseline: 1.5111x; 1.1486x over previous
#include <cuda_runtime.h>
#include <cuda_bf16.h>
#include <cstdint>

// Problem constants
#define N_EMBED 512
#define DIMQ    64          // IN_MEM*OUT_MEM
#define NROWS   4096        // IN_G*OUT_G
#define KDIM    512
#define NDIM    512
#define BDIM    8192
#define QBLK2   (NROWS / 16)   // 256 quantize blocks (16 rows each)
#define XBLKS   2048           // xsplit blocks

// Scratch (no cudaMalloc allowed)
__device__ __nv_bfloat16  d_WtHi[NDIM * KDIM];    // W^T hi  [n][k]
__device__ __nv_bfloat16  d_WtLo[NDIM * KDIM];    // W^T lo  [n][k]
__device__ __nv_bfloat16  d_XHi[BDIM * KDIM];     // x hi    [m][k]
__device__ __nv_bfloat16  d_XLo[BDIM * KDIM];     // x lo    [m][k]
__device__ double         d_diff_blk[QBLK2];      // per-block diff partials

// ---------------------------------------------------------------------------
// helpers
// ---------------------------------------------------------------------------
__device__ __forceinline__ uint32_t smem_u32(const void* p) {
    uint32_t a;
    asm("{ .reg .u64 t; cvta.to.shared.u64 t, %1; cvt.u32.u64 %0, t; }" : "=r"(a) : "l"(p));
    return a;
}
__device__ __forceinline__ void split2(float a, float b, uint32_t& h, uint32_t& l) {
    __nv_bfloat16 ah = __float2bfloat16_rn(a);
    __nv_bfloat16 bh = __float2bfloat16_rn(b);
    __nv_bfloat16 al = __float2bfloat16_rn(a - __bfloat162float(ah));
    __nv_bfloat16 bl = __float2bfloat16_rn(b - __bfloat162float(bh));
    __nv_bfloat162 hv; hv.x = ah; hv.y = bh;
    __nv_bfloat162 lv; lv.x = al; lv.y = bl;
    h = *(uint32_t*)&hv; l = *(uint32_t*)&lv;
}
__device__ __forceinline__ void ldsm4(uint32_t* r, uint32_t addr) {
    asm volatile("ldmatrix.sync.aligned.m8n8.x4.shared.b16 {%0,%1,%2,%3}, [%4];"
                 : "=r"(r[0]), "=r"(r[1]), "=r"(r[2]), "=r"(r[3]) : "r"(addr));
}
__device__ __forceinline__ void mma16816(float* c, const uint32_t* a,
                                         uint32_t b0, uint32_t b1) {
    asm volatile("mma.sync.aligned.m16n8k16.row.col.f32.bf16.bf16.f32 "
                 "{%0,%1,%2,%3}, {%4,%5,%6,%7}, {%8,%9}, {%0,%1,%2,%3};"
                 : "+f"(c[0]), "+f"(c[1]), "+f"(c[2]), "+f"(c[3])
                 : "r"(a[0]), "r"(a[1]), "r"(a[2]), "r"(a[3]), "r"(b0), "r"(b1));
}

// ---------------------------------------------------------------------------
// fused pre-pass: blocks [0,256) = quantize (16 rows each);
//                 blocks [256,2304) = xsplit (x fp32 -> bf16 hi/lo planes).
// ---------------------------------------------------------------------------
__global__ __launch_bounds__(256) void prepass_kernel(
    const float* __restrict__ w,        // [4096,64] flat
    const float* __restrict__ embed,    // [64,512]
    const float* __restrict__ x)        // [8192,512]
{
    const int tid = threadIdx.x;

    if (blockIdx.x >= QBLK2) {
        // ---- xsplit path ----
        const size_t base = ((size_t)(blockIdx.x - QBLK2) * 256 + tid) * 8;
        float4 v0 = __ldg((const float4*)(x + base));
        float4 v1 = __ldg((const float4*)(x + base + 4));
        uint32_t h[4], l[4];
        split2(v0.x, v0.y, h[0], l[0]);
        split2(v0.z, v0.w, h[1], l[1]);
        split2(v1.x, v1.y, h[2], l[2]);
        split2(v1.z, v1.w, h[3], l[3]);
        *(uint4*)&d_XHi[base] = make_uint4(h[0], h[1], h[2], h[3]);
        *(uint4*)&d_XLo[base] = make_uint4(l[0], l[1], l[2], l[3]);
        return;
    }

    // ---- quantize path: 16 rows, thread = 2 rows x 16 codes ----
    __shared__ float  ws[16][DIMQ];
    __shared__ double blk_diff[8];

    const int ty  = tid >> 5;           // warp id -> row pair
    const int tx  = tid & 31;           // lane
    const int row0 = blockIdx.x * 16;

    {   // w tile: thread -> row tid>>4, cols (tid&15)*4
        const int r = tid >> 4;
        const int c = (tid & 15) * 4;
        *(float4*)&ws[r][c] = __ldg((const float4*)(w + (size_t)(row0 + r) * DIMQ + c));
    }
    __syncthreads();

    float acc[2][16];
    float e2acc[16];
    #pragma unroll
    for (int c = 0; c < 16; ++c) e2acc[c] = 0.f;
    #pragma unroll
    for (int r = 0; r < 2; ++r)
        #pragma unroll
        for (int c = 0; c < 16; ++c) acc[r][c] = 0.f;

    #pragma unroll 4
    for (int d = 0; d < DIMQ; ++d) {
        float e[16];
        #pragma unroll
        for (int g = 0; g < 4; ++g)
            *(float4*)&e[g * 4] = __ldg((const float4*)(embed + d * N_EMBED + g * 128 + tx * 4));
        float wv0 = ws[ty * 2][d];
        float wv1 = ws[ty * 2 + 1][d];
        #pragma unroll
        for (int c = 0; c < 16; ++c) {
            e2acc[c]  += e[c] * e[c];
            acc[0][c] += wv0 * e[c];
            acc[1][c] += wv1 * e[c];
        }
    }

    float diff_local = 0.f;
    #pragma unroll
    for (int r = 0; r < 2; ++r) {
        float best = 3.4e38f;
        int   bidx = 0;
        #pragma unroll
        for (int g = 0; g < 4; ++g)
            #pragma unroll
            for (int j = 0; j < 4; ++j) {
                int c = g * 128 + tx * 4 + j;           // ascending within thread
                float s = e2acc[g * 4 + j] - 2.f * acc[r][g * 4 + j];
                if (s < best) { best = s; bidx = c; }   // strict < keeps lowest c
            }
        #pragma unroll
        for (int off = 16; off >= 1; off >>= 1) {
            float ob = __shfl_xor_sync(0xffffffffu, best, off);
            int   oi = __shfl_xor_sync(0xffffffffu, bidx, off);
            if (ob < best || (ob == best && oi < bidx)) { best = ob; bidx = oi; }
        }
        // all lanes agree on bidx for this row
        const int rl  = ty * 2 + r;
        const int row = row0 + rl;
        const int ig = row >> 6;
        const int og = row & 63;
        const int om = tx & 7;
        const int i0 = (tx >> 3) * 2;
        const int d0 = i0 * 8 + om;
        const int d1 = d0 + 8;
        float q0 = __ldg(embed + d0 * N_EMBED + bidx);
        float q1 = __ldg(embed + d1 * N_EMBED + bidx);
        float w0 = ws[rl][d0], w1 = ws[rl][d1];
        float df0 = q0 - w0, df1 = q1 - w1;
        diff_local += df0 * df0 + df1 * df1;
        uint32_t h, l;
        split2(q0, q1, h, l);
        const size_t off_nk = (size_t)(og * 8 + om) * KDIM + ig * 8 + i0;
        *(uint32_t*)&d_WtHi[off_nk] = h;
        *(uint32_t*)&d_WtLo[off_nk] = l;
    }

    #pragma unroll
    for (int off = 16; off >= 1; off >>= 1)
        diff_local += __shfl_xor_sync(0xffffffffu, diff_local, off);
    if (tx == 0) blk_diff[ty] = (double)diff_local;
    __syncthreads();
    if (tid == 0) {
        double s = 0.0;
        #pragma unroll
        for (int i = 0; i < 8; ++i) s += blk_diff[i];
        d_diff_blk[blockIdx.x] = s;
    }
}

// ---------------------------------------------------------------------------
// HMMA GEMM: C = x @ W via bf16 split (3 products), fp32 accum.
// CTA 128x128, 8 warps (warp tile 32x64), BK=32, 16 chunks, double-buffered
// smem; all operands via cp.async (pre-split planes). 2 CTAs/SM.
// CTA(0,0) reduces the 256 diff partials with 256 parallel threads.
// ---------------------------------------------------------------------------
#define BK      32
#define NCH     (KDIM / BK)         // 16
#define RS      80                  // smem row stride bytes (64B data + pad)
#define MATB    (128 * RS)          // 10240 per matrix
#define STAGEB  (4 * MATB)          // 40960 per stage (Ahi, Alo, Whi, Wlo)
#define SMEMB   (2 * STAGEB)        // 81920

__global__ __launch_bounds__(256, 2) void gemm_mma_kernel(
    float* __restrict__ C,          // res [B,512] (+ diff scalar)
    long n_res, long out_total)
{
    extern __shared__ char smem[];
    __shared__ double sdiff[8];
    const uint32_t sb = smem_u32(smem);
    const int tid  = threadIdx.x;
    const int lane = tid & 31;
    const int wid  = tid >> 5;
    const int m0 = blockIdx.y * 128;
    const int n0 = blockIdx.x * 128;
    const int wm = (wid & 3) * 32;
    const int wn = (wid >> 2) * 64;

    // parallel diff reduction on CTA (0,0): one load per thread, tree-reduce
    if (blockIdx.x == 0 && blockIdx.y == 0 && out_total > n_res) {
        double v = d_diff_blk[tid];                 // QBLK2 == blockDim == 256
        #pragma unroll
        for (int off = 16; off >= 1; off >>= 1)
            v += __shfl_xor_sync(0xffffffffu, v, off);
        if (lane == 0) sdiff[wid] = v;
        __syncthreads();
        if (tid == 0) {
            double s = 0.0;
            #pragma unroll
            for (int i = 0; i < 8; ++i) s += sdiff[i];
            C[n_res] = (float)(s * (1.0 / (double)(NROWS * DIMQ)));
        }
    }

    const uint32_t aOff = (uint32_t)(wm + (lane & 15)) * RS + ((lane >> 4) * 16);
    const uint32_t bOff = (uint32_t)(wn + ((lane >> 4) * 8) + (lane & 7)) * RS
                        + (((lane >> 3) & 1) * 16);

    // cp.async sources: half the threads handle hi planes, half lo planes
    const int prow = tid & 127;
    const __nv_bfloat16* aG = ((tid < 128) ? d_XHi : d_XLo) + (size_t)(m0 + prow) * KDIM;
    const __nv_bfloat16* wG = ((tid < 128) ? d_WtHi : d_WtLo) + (size_t)(n0 + prow) * KDIM;
    const uint32_t aSt = ((tid < 128) ? 0u : (uint32_t)MATB) + (uint32_t)prow * RS;
    const uint32_t wSt = aSt + 2 * MATB;

    float acc[2][8][4];
    #pragma unroll
    for (int mt = 0; mt < 2; ++mt)
        #pragma unroll
        for (int nt = 0; nt < 8; ++nt)
            #pragma unroll
            for (int q = 0; q < 4; ++q) acc[mt][nt][q] = 0.f;

    #define CPALL(kc, stage) do {                                                 \
        uint32_t _ad = sb + (stage) * STAGEB + aSt;                               \
        uint32_t _wd = sb + (stage) * STAGEB + wSt;                               \
        const char* _as = (const char*)(aG + (kc) * BK);                          \
        const char* _ws = (const char*)(wG + (kc) * BK);                          \
        _Pragma("unroll")                                                         \
        for (int _j = 0; _j < 4; ++_j)                                            \
            asm volatile("cp.async.cg.shared.global [%0], [%1], 16;"              \
                         :: "r"(_ad + _j * 16), "l"(_as + _j * 16) : "memory");   \
        _Pragma("unroll")                                                         \
        for (int _j = 0; _j < 4; ++_j)                                            \
            asm volatile("cp.async.cg.shared.global [%0], [%1], 16;"              \
                         :: "r"(_wd + _j * 16), "l"(_ws + _j * 16) : "memory");   \
        asm volatile("cp.async.commit_group;" ::: "memory");                      \
    } while (0)

    #define COMPUTE(stage) do {                                                   \
        uint32_t _Ab = sb + (stage) * STAGEB;                                     \
        uint32_t _Bb = _Ab + 2 * MATB;                                            \
        _Pragma("unroll")                                                         \
        for (int _ks = 0; _ks < 2; ++_ks) {                                       \
            uint32_t _ahi[2][4], _alo[2][4], _bf[4][4];                           \
            _Pragma("unroll")                                                     \
            for (int _mt = 0; _mt < 2; ++_mt) {                                   \
                uint32_t _ad = _Ab + aOff + _mt * 16 * RS + _ks * 32;             \
                ldsm4(_ahi[_mt], _ad);                                            \
                ldsm4(_alo[_mt], _ad + MATB);                                     \
            }                                                                     \
            _Pragma("unroll")                                                     \
            for (int _p = 0; _p < 4; ++_p)                                        \
                ldsm4(_bf[_p], _Bb + bOff + _p * 16 * RS + _ks * 32);             \
            _Pragma("unroll")                                                     \
            for (int _mt = 0; _mt < 2; ++_mt)                                     \
                _Pragma("unroll")                                                 \
                for (int _nt = 0; _nt < 8; ++_nt) {                               \
                    uint32_t _b0 = _bf[_nt >> 1][(_nt & 1) * 2];                  \
                    uint32_t _b1 = _bf[_nt >> 1][(_nt & 1) * 2 + 1];              \
                    mma16816(acc[_mt][_nt], _ahi[_mt], _b0, _b1);                 \
                    mma16816(acc[_mt][_nt], _alo[_mt], _b0, _b1);                 \
                }                                                                 \
            _Pragma("unroll")                                                     \
            for (int _p = 0; _p < 4; ++_p)                                        \
                ldsm4(_bf[_p], _Bb + MATB + bOff + _p * 16 * RS + _ks * 32);      \
            _Pragma("unroll")                                                     \
            for (int _mt = 0; _mt < 2; ++_mt)                                     \
                _Pragma("unroll")                                                 \
                for (int _nt = 0; _nt < 8; ++_nt)                                 \
                    mma16816(acc[_mt][_nt], _ahi[_mt],                            \
                             _bf[_nt >> 1][(_nt & 1) * 2],                        \
                             _bf[_nt >> 1][(_nt & 1) * 2 + 1]);                   \
        }                                                                         \
    } while (0)

    CPALL(0, 0);
    asm volatile("cp.async.wait_group 0;" ::: "memory");
    __syncthreads();

    for (int kc = 0; kc < NCH; ++kc) {
        const int st = kc & 1;
        if (kc + 1 < NCH) CPALL(kc + 1, st ^ 1);
        COMPUTE(st);
        if (kc + 1 < NCH) {
            asm volatile("cp.async.wait_group 0;" ::: "memory");
            __syncthreads();
        }
    }

    #pragma unroll
    for (int mt = 0; mt < 2; ++mt) {
        int row = m0 + wm + mt * 16 + (lane >> 2);
        #pragma unroll
        for (int nt = 0; nt < 8; ++nt) {
            int col = n0 + wn + nt * 8 + (lane & 3) * 2;
            *(float2*)&C[(size_t)row * NDIM + col] =
                make_float2(acc[mt][nt][0], acc[mt][nt][1]);
            *(float2*)&C[(size_t)(row + 8) * NDIM + col] =
                make_float2(acc[mt][nt][2], acc[mt][nt][3]);
        }
    }
}

// ---------------------------------------------------------------------------
// launch: 2 kernels
// ---------------------------------------------------------------------------
extern "C" void kernel_launch(void* const* d_in, const int* in_sizes, int n_in,
                              void* d_out, int out_size) {
    const float* x      = (const float*)d_in[0];
    const float* weight = (const float*)d_in[1];
    const float* embed  = (const float*)d_in[2];
    float* out = (float*)d_out;

    const int b = in_sizes[0] / KDIM;              // 8192

    prepass_kernel<<<QBLK2 + XBLKS, 256>>>(weight, embed, x);

    static int smem_set = 0;
    if (!smem_set) {
        cudaFuncSetAttribute(gemm_mma_kernel,
                             cudaFuncAttributeMaxDynamicSharedMemorySize, SMEMB);
        smem_set = 1;
    }
    dim3 grid(NDIM / 128, b / 128);                // (4, 64)
    gemm_mma_kernel<<<grid, 256, SMEMB>>>(out, (long)b * NDIM, (long)out_size);
}